// round 12
// baseline (speedup 1.0000x reference)
#include <cuda_runtime.h>

// CrossCompressUnit: rank-1 cross compress.
// v_out = v * (e.w_vv) + e * (v.w_ev) + b_v
// e_out = v * (e.w_ve) + e * (v.w_ee) + b_e
//
// 2 rows per warp per iteration: lanes 0-15 own row r (8 floats/lane),
// lanes 16-31 own row r+1. 256-bit streaming loads (ld.global.cs.v8.b32),
// packed reduction confined to 16-lane halves (9 SHFLs / 2 rows),
// next-row-pair prefetch, .cs stores.

#define D 128

__device__ __forceinline__ void ldg_v8_cs(const float* p, float* r) {
    asm volatile("ld.global.cs.v8.b32 {%0,%1,%2,%3,%4,%5,%6,%7}, [%8];"
                 : "=f"(r[0]), "=f"(r[1]), "=f"(r[2]), "=f"(r[3]),
                   "=f"(r[4]), "=f"(r[5]), "=f"(r[6]), "=f"(r[7])
                 : "l"(p));
}

__device__ __forceinline__ float dot8(const float* a, const float* w) {
    float s = a[0] * w[0];
    #pragma unroll
    for (int i = 1; i < 8; i++) s = fmaf(a[i], w[i], s);
    return s;
}

__global__ __launch_bounds__(256)
void cross_compress_kernel(const float* __restrict__ v,
                           const float* __restrict__ e,
                           const float* __restrict__ w_vv,
                           const float* __restrict__ w_ev,
                           const float* __restrict__ w_ve,
                           const float* __restrict__ w_ee,
                           const float* __restrict__ b_v,
                           const float* __restrict__ b_e,
                           float* __restrict__ out,   // [2*B*D]: v_out then e_out
                           int B)
{
    const unsigned FULL = 0xffffffffu;
    const int lane            = threadIdx.x & 31;
    const int warp_in_block   = threadIdx.x >> 5;
    const int warps_per_block = blockDim.x >> 5;
    const int gwarp  = blockIdx.x * warps_per_block + warp_in_block;
    const int nwarps = gridDim.x * warps_per_block;

    const int half = (lane >> 4) & 1;   // which row of the pair
    const int hl   = lane & 15;         // lane within half
    const int c    = hl * 8;            // column base (8 floats per lane)

    // Weight slices in registers (4 x 8 floats = 32 regs).
    float wvv8[8], wev8[8], wve8[8], wee8[8];
    *reinterpret_cast<float4*>(&wvv8[0]) = *reinterpret_cast<const float4*>(w_vv + c);
    *reinterpret_cast<float4*>(&wvv8[4]) = *reinterpret_cast<const float4*>(w_vv + c + 4);
    *reinterpret_cast<float4*>(&wev8[0]) = *reinterpret_cast<const float4*>(w_ev + c);
    *reinterpret_cast<float4*>(&wev8[4]) = *reinterpret_cast<const float4*>(w_ev + c + 4);
    *reinterpret_cast<float4*>(&wve8[0]) = *reinterpret_cast<const float4*>(w_ve + c);
    *reinterpret_cast<float4*>(&wve8[4]) = *reinterpret_cast<const float4*>(w_ve + c + 4);
    *reinterpret_cast<float4*>(&wee8[0]) = *reinterpret_cast<const float4*>(w_ee + c);
    *reinterpret_cast<float4*>(&wee8[4]) = *reinterpret_cast<const float4*>(w_ee + c + 4);

    float* out_v = out;
    float* out_e = out + (size_t)B * D;

    const bool hi8 = (lane & 8) != 0;
    const bool hi4 = (lane & 4) != 0;
    const int  hbase = lane & 16;

    const int stride = nwarps * 2;
    int row = gwarp * 2;

    float vc[8], ec[8];
    #pragma unroll
    for (int i = 0; i < 8; i++) { vc[i] = 0.f; ec[i] = 0.f; }
    if (row + half < B) {
        const size_t base = (size_t)(row + half) * D + c;
        ldg_v8_cs(v + base, vc);
        ldg_v8_cs(e + base, ec);
    }

    for (; row < B; row += stride) {
        // Prefetch next row pair (2 x LDG.256 in flight during reduction).
        const int nrow = row + stride;
        float vn[8], en[8];
        #pragma unroll
        for (int i = 0; i < 8; i++) { vn[i] = 0.f; en[i] = 0.f; }
        if (nrow + half < B) {
            const size_t nbase = (size_t)(nrow + half) * D + c;
            ldg_v8_cs(v + nbase, vn);
            ldg_v8_cs(e + nbase, en);
        }

        // Per-lane partials (this lane's row = row + half).
        float p0 = dot8(ec, wvv8);   // e . w_vv
        float p1 = dot8(vc, wev8);   // v . w_ev
        float p2 = dot8(ec, wve8);   // e . w_ve
        float p3 = dot8(vc, wee8);   // v . w_ee

        // Reduction within each 16-lane half (offsets <= 8 never cross halves).
        // Stage 1 (xor8): bit3=0 lanes accumulate p0/p1, bit3=1 accumulate p2/p3.
        float r1 = __shfl_xor_sync(FULL, hi8 ? p0 : p2, 8);
        float u  = (hi8 ? p2 : p0) + r1;
        float r2 = __shfl_xor_sync(FULL, hi8 ? p1 : p3, 8);
        float w  = (hi8 ? p3 : p1) + r2;
        // Stage 2 (xor4): 4-lane subgroup (bit3,bit2) owns dot (p0,p1,p2,p3).
        float r3 = __shfl_xor_sync(FULL, hi4 ? u : w, 4);
        float s  = (hi4 ? w : u) + r3;
        // Stages 3-4: butterfly within 4-lane subgroups.
        s += __shfl_xor_sync(FULL, s, 2);
        s += __shfl_xor_sync(FULL, s, 1);
        // Broadcast the four dots from this half.
        const float d_vv = __shfl_sync(FULL, s, hbase + 0);
        const float d_ev = __shfl_sync(FULL, s, hbase + 4);
        const float d_ve = __shfl_sync(FULL, s, hbase + 8);
        const float d_ee = __shfl_sync(FULL, s, hbase + 12);

        if (row + half < B) {
            // Biases per-iteration via read-only cache (L1-hot, saves 16 regs).
            const float4 bv0 = __ldg(reinterpret_cast<const float4*>(b_v + c));
            const float4 bv1 = __ldg(reinterpret_cast<const float4*>(b_v + c + 4));
            const float4 be0 = __ldg(reinterpret_cast<const float4*>(b_e + c));
            const float4 be1 = __ldg(reinterpret_cast<const float4*>(b_e + c + 4));

            const size_t base = (size_t)(row + half) * D + c;
            float4 o;
            o.x = fmaf(vc[0], d_vv, fmaf(ec[0], d_ev, bv0.x));
            o.y = fmaf(vc[1], d_vv, fmaf(ec[1], d_ev, bv0.y));
            o.z = fmaf(vc[2], d_vv, fmaf(ec[2], d_ev, bv0.z));
            o.w = fmaf(vc[3], d_vv, fmaf(ec[3], d_ev, bv0.w));
            __stcs(reinterpret_cast<float4*>(out_v + base), o);
            o.x = fmaf(vc[4], d_vv, fmaf(ec[4], d_ev, bv1.x));
            o.y = fmaf(vc[5], d_vv, fmaf(ec[5], d_ev, bv1.y));
            o.z = fmaf(vc[6], d_vv, fmaf(ec[6], d_ev, bv1.z));
            o.w = fmaf(vc[7], d_vv, fmaf(ec[7], d_ev, bv1.w));
            __stcs(reinterpret_cast<float4*>(out_v + base + 4), o);

            o.x = fmaf(vc[0], d_ve, fmaf(ec[0], d_ee, be0.x));
            o.y = fmaf(vc[1], d_ve, fmaf(ec[1], d_ee, be0.y));
            o.z = fmaf(vc[2], d_ve, fmaf(ec[2], d_ee, be0.z));
            o.w = fmaf(vc[3], d_ve, fmaf(ec[3], d_ee, be0.w));
            __stcs(reinterpret_cast<float4*>(out_e + base), o);
            o.x = fmaf(vc[4], d_ve, fmaf(ec[4], d_ee, be1.x));
            o.y = fmaf(vc[5], d_ve, fmaf(ec[5], d_ee, be1.y));
            o.z = fmaf(vc[6], d_ve, fmaf(ec[6], d_ee, be1.z));
            o.w = fmaf(vc[7], d_ve, fmaf(ec[7], d_ee, be1.w));
            __stcs(reinterpret_cast<float4*>(out_e + base + 4), o);
        }

        #pragma unroll
        for (int i = 0; i < 8; i++) { vc[i] = vn[i]; ec[i] = en[i]; }
    }
}

extern "C" void kernel_launch(void* const* d_in, const int* in_sizes, int n_in,
                              void* d_out, int out_size)
{
    const float* v    = (const float*)d_in[0];
    const float* e    = (const float*)d_in[1];
    const float* w_vv = (const float*)d_in[2];
    const float* w_ev = (const float*)d_in[3];
    const float* w_ve = (const float*)d_in[4];
    const float* w_ee = (const float*)d_in[5];
    const float* b_v  = (const float*)d_in[6];
    const float* b_e  = (const float*)d_in[7];
    float* out = (float*)d_out;

    const int B = in_sizes[0] / D;   // rows

    const int threads = 256;
    const int warps_per_block = threads / 32;   // 8
    // 8 rows per warp (4 iterations of 2 rows).
    int blocks = (B + warps_per_block * 8 - 1) / (warps_per_block * 8);
    if (blocks < 1) blocks = 1;

    cross_compress_kernel<<<blocks, threads>>>(v, e, w_vv, w_ev, w_ve, w_ee,
                                               b_v, b_e, out, B);
}

// round 13
// speedup vs baseline: 1.0748x; 1.0748x over previous
#include <cuda_runtime.h>

// CrossCompressUnit: rank-1 cross compress.  [FINAL — R4 configuration]
// v_out = v * (e.w_vv) + e * (v.w_ev) + b_v
// e_out = v * (e.w_ve) + e * (v.w_ee) + b_e
//
// One warp per row. Packed 4-way warp reduction (10 SHFLs instead of 20):
//   xor16 merges (p0,p2) -> u and (p1,p3) -> w  (2 SHFL)
//   xor8 repartitions so 8-lane group g owns dot g (1 SHFL)
//   3-stage butterfly within groups (3 SHFL)
//   4 broadcasts (4 SHFL)
// Next row's loads are prefetched before the current row's reduction so
// DRAM requests stay in flight behind the shuffle chain. Streaming (.cs)
// loads and stores. Measured: 38.5us in-kernel, DRAM 71.5% — the mixed
// read/write HBM plateau for this 1:1 R/W stream on GB300.

#define D 128

__device__ __forceinline__ float dot4(float4 a, float4 b) {
    return fmaf(a.x, b.x, fmaf(a.y, b.y, fmaf(a.z, b.z, a.w * b.w)));
}

__global__ __launch_bounds__(256)
void cross_compress_kernel(const float* __restrict__ v,
                           const float* __restrict__ e,
                           const float* __restrict__ w_vv,
                           const float* __restrict__ w_ev,
                           const float* __restrict__ w_ve,
                           const float* __restrict__ w_ee,
                           const float* __restrict__ b_v,
                           const float* __restrict__ b_e,
                           float* __restrict__ out,   // [2*B*D]: v_out then e_out
                           int B)
{
    const unsigned FULL = 0xffffffffu;
    const int lane            = threadIdx.x & 31;
    const int warp_in_block   = threadIdx.x >> 5;
    const int warps_per_block = blockDim.x >> 5;
    const int gwarp  = blockIdx.x * warps_per_block + warp_in_block;
    const int nwarps = gridDim.x * warps_per_block;

    const int c = lane * 4;   // column base for this lane

    // Per-lane weight slices, register-resident (3KB total, L2-hot).
    const float4 wvv = *reinterpret_cast<const float4*>(w_vv + c);
    const float4 wev = *reinterpret_cast<const float4*>(w_ev + c);
    const float4 wve = *reinterpret_cast<const float4*>(w_ve + c);
    const float4 wee = *reinterpret_cast<const float4*>(w_ee + c);
    const float4 bv  = *reinterpret_cast<const float4*>(b_v  + c);
    const float4 be  = *reinterpret_cast<const float4*>(b_e  + c);

    float* out_v = out;
    float* out_e = out + (size_t)B * D;

    const bool hi16 = (lane & 16) != 0;
    const bool hi8  = (lane & 8)  != 0;

    int row = gwarp;
    float4 v_cur = make_float4(0.f, 0.f, 0.f, 0.f);
    float4 e_cur = v_cur;
    if (row < B) {
        const size_t base = (size_t)row * D + c;
        v_cur = __ldcs(reinterpret_cast<const float4*>(v + base));
        e_cur = __ldcs(reinterpret_cast<const float4*>(e + base));
    }

    for (; row < B; row += nwarps) {
        // Prefetch next row: 2 LDG.128 in flight during the reduction below.
        const int nrow = row + nwarps;
        float4 v_nxt = make_float4(0.f, 0.f, 0.f, 0.f);
        float4 e_nxt = v_nxt;
        if (nrow < B) {
            const size_t nbase = (size_t)nrow * D + c;
            v_nxt = __ldcs(reinterpret_cast<const float4*>(v + nbase));
            e_nxt = __ldcs(reinterpret_cast<const float4*>(e + nbase));
        }

        // Per-lane partials.
        float p0 = dot4(e_cur, wvv);   // e . w_vv
        float p1 = dot4(v_cur, wev);   // v . w_ev
        float p2 = dot4(e_cur, wve);   // e . w_ve
        float p3 = dot4(v_cur, wee);   // v . w_ee

        // Stage 1 (xor16): lanes<16 accumulate p0/p1, lanes>=16 accumulate p2/p3.
        float r1 = __shfl_xor_sync(FULL, hi16 ? p0 : p2, 16);
        float u  = (hi16 ? p2 : p0) + r1;
        float r2 = __shfl_xor_sync(FULL, hi16 ? p1 : p3, 16);
        float w  = (hi16 ? p3 : p1) + r2;

        // Stage 2 (xor8): 8-lane group g ends up owning dot g.
        float r3 = __shfl_xor_sync(FULL, hi8 ? u : w, 8);
        float s  = (hi8 ? w : u) + r3;

        // Stages 3-5: butterfly within 8-lane groups.
        s += __shfl_xor_sync(FULL, s, 4);
        s += __shfl_xor_sync(FULL, s, 2);
        s += __shfl_xor_sync(FULL, s, 1);

        // Broadcast the four dots to all lanes.
        const float d_vv = __shfl_sync(FULL, s, 0);
        const float d_ev = __shfl_sync(FULL, s, 8);
        const float d_ve = __shfl_sync(FULL, s, 16);
        const float d_ee = __shfl_sync(FULL, s, 24);

        float4 vo, eo;
        vo.x = fmaf(v_cur.x, d_vv, fmaf(e_cur.x, d_ev, bv.x));
        vo.y = fmaf(v_cur.y, d_vv, fmaf(e_cur.y, d_ev, bv.y));
        vo.z = fmaf(v_cur.z, d_vv, fmaf(e_cur.z, d_ev, bv.z));
        vo.w = fmaf(v_cur.w, d_vv, fmaf(e_cur.w, d_ev, bv.w));
        eo.x = fmaf(v_cur.x, d_ve, fmaf(e_cur.x, d_ee, be.x));
        eo.y = fmaf(v_cur.y, d_ve, fmaf(e_cur.y, d_ee, be.y));
        eo.z = fmaf(v_cur.z, d_ve, fmaf(e_cur.z, d_ee, be.z));
        eo.w = fmaf(v_cur.w, d_ve, fmaf(e_cur.w, d_ee, be.w));

        const size_t base = (size_t)row * D + c;
        __stcs(reinterpret_cast<float4*>(out_v + base), vo);
        __stcs(reinterpret_cast<float4*>(out_e + base), eo);

        v_cur = v_nxt;
        e_cur = e_nxt;
    }
}

extern "C" void kernel_launch(void* const* d_in, const int* in_sizes, int n_in,
                              void* d_out, int out_size)
{
    const float* v    = (const float*)d_in[0];
    const float* e    = (const float*)d_in[1];
    const float* w_vv = (const float*)d_in[2];
    const float* w_ev = (const float*)d_in[3];
    const float* w_ve = (const float*)d_in[4];
    const float* w_ee = (const float*)d_in[5];
    const float* b_v  = (const float*)d_in[6];
    const float* b_e  = (const float*)d_in[7];
    float* out = (float*)d_out;

    const int B = in_sizes[0] / D;   // rows

    const int threads = 256;
    const int warps_per_block = threads / 32;   // 8
    // 8 rows per warp -> enough loop trips for prefetch pipelining.
    int blocks = (B + warps_per_block * 8 - 1) / (warps_per_block * 8);
    if (blocks < 1) blocks = 1;

    cross_compress_kernel<<<blocks, threads>>>(v, e, w_vv, w_ev, w_ve, w_ee,
                                               b_v, b_e, out, B);
}